// round 1
// baseline (speedup 1.0000x reference)
#include <cuda_runtime.h>

#define NROW 1024
#define HDIM 300
#define MID  100
#define NJ   1025           // N+1 columns
#define OUT_LD 1025
#define S2_PITCH 1100       // floats, multiple of 4, covers padded j reads up to 1088

// ---- device scratch (zero-initialized at module load; fully rewritten each run) ----
__device__ __align__(16) float g_s1h[NROW * MID];        // [i][m] = 0.5*s1
__device__ __align__(16) float g_s2hT[MID * S2_PITCH];   // [m][j] = 0.5*(s2+b1)  (transposed)
__device__ float g_w2h[MID];
__device__ float g_C[1];
__device__ float g_rowloss[NROW];

__device__ __forceinline__ float tanh_ap(float x) {
    float r;
    asm("tanh.approx.f32 %0, %1;" : "=f"(r) : "f"(x));
    return r;
}

// ---------------- k0: tiny prep: w2h, C = b2 + 0.5*sum(w2), s2hT[:,0] = 0.5*b1 ----------------
__global__ void k0_prep(const float* __restrict__ W2, const float* __restrict__ b1,
                        const float* __restrict__ b2) {
    __shared__ float red[128];
    int t = threadIdx.x;
    float w = 0.f;
    if (t < MID) {
        w = W2[t];
        g_w2h[t] = 0.5f * w;
        g_s2hT[t * S2_PITCH + 0] = 0.5f * b1[t];   // pm row 0 is zeros -> only bias
    }
    red[t] = w;
    __syncthreads();
    for (int s = 64; s > 0; s >>= 1) {
        if (t < s) red[t] += red[t + s];
        __syncthreads();
    }
    if (t == 0) g_C[0] = b2[0] + 0.5f * red[0];
}

// ---------------- k1: dual GEMM: s1h[1024][100] and s2hT[100][1..1024] ----------------
// Virtual rows: r<1024 -> s1 (W1 first half); r>=1024 -> s2 row j=r-1023 (W1 second half, +b1)
#define HC 20
__global__ void __launch_bounds__(256) k1_gemm(const float* __restrict__ sent,
                                               const float* __restrict__ W1,
                                               const float* __restrict__ b1) {
    __shared__ float rs[64][HC + 1];   // row tile (odd pitch -> conflict-free)
    __shared__ float ws[HC][MID];      // W1 chunk transposed
    int tid = threadIdx.x;
    int tx  = tid & 63;                // row within tile (warp = 32 consecutive tx, same ty)
    int ty  = tid >> 6;                // 0..3 -> m = ty + 4k
    int row0 = blockIdx.x * 64;        // 32 blocks x 64 rows = 2048 rows
    bool isS1 = (row0 < NROW);
    int woff = isS1 ? 0 : HDIM;
    const float* src = sent + (size_t)(isS1 ? row0 : row0 - NROW) * HDIM;

    float acc[25];
#pragma unroll
    for (int k = 0; k < 25; k++) acc[k] = 0.f;

    for (int hc = 0; hc < HDIM; hc += HC) {
        for (int q = tid; q < 64 * HC; q += 256) {
            int rr = q / HC, h = q % HC;
            rs[rr][h] = src[rr * HDIM + hc + h];
        }
        for (int q = tid; q < MID * HC; q += 256) {
            int m = q / HC, h = q % HC;
            ws[h][m] = W1[m * (2 * HDIM) + woff + hc + h];
        }
        __syncthreads();
#pragma unroll
        for (int h = 0; h < HC; h++) {
            float rv = rs[tx][h];
#pragma unroll
            for (int k = 0; k < 25; k++)
                acc[k] = fmaf(rv, ws[h][ty + 4 * k], acc[k]);
        }
        __syncthreads();
    }

    if (isS1) {
        int i = row0 + tx;
#pragma unroll
        for (int k = 0; k < 25; k++)
            g_s1h[i * MID + ty + 4 * k] = 0.5f * acc[k];
    } else {
        int j = row0 - NROW + tx + 1;   // 1..1024
#pragma unroll
        for (int k = 0; k < 25; k++) {
            int m = ty + 4 * k;
            g_s2hT[m * S2_PITCH + j] = 0.5f * (acc[k] + b1[m]);
        }
    }
}

// ---------------- k2: pairwise scores (MUFU.TANH bound) ----------------
// Tile: 32 i x 64 j. Thread: 1 i x 8 j. scores written straight into d_out+1.
__global__ void __launch_bounds__(256) k2_scores(float* __restrict__ outS) {
    __shared__ float  s1s[32][104];
    __shared__ float4 s2t[MID][18];    // 72-float pitch, tile transposed [m][j]
    __shared__ float  w2s[MID];
    __shared__ float  csh;

    int tid = threadIdx.x;
    int i0 = blockIdx.y * 32;
    int j0 = blockIdx.x * 64;

    for (int q = tid; q < 32 * MID; q += 256) {
        int r = q / MID, m = q % MID;
        s1s[r][m] = g_s1h[(i0 + r) * MID + m];
    }
    {
        const float4* src4 = (const float4*)g_s2hT;
        int jb4 = j0 >> 2;
        for (int q = tid; q < MID * 16; q += 256) {
            int m = q >> 4, jj = q & 15;
            s2t[m][jj] = src4[m * (S2_PITCH / 4) + jb4 + jj];
        }
    }
    if (tid < MID) w2s[tid] = g_w2h[tid];
    if (tid == 0) csh = g_C[0];
    __syncthreads();

    int ti = tid >> 3;          // 0..31 (i within tile)
    int tg = tid & 7;           // j group: 8 consecutive j
    float acc[8];
#pragma unroll
    for (int c = 0; c < 8; c++) acc[c] = 0.f;

#pragma unroll 4
    for (int m = 0; m < MID; m++) {
        float a = s1s[ti][m];
        float w = w2s[m];
        float4 u = s2t[m][tg * 2];
        float4 v = s2t[m][tg * 2 + 1];
        acc[0] = fmaf(w, tanh_ap(a + u.x), acc[0]);
        acc[1] = fmaf(w, tanh_ap(a + u.y), acc[1]);
        acc[2] = fmaf(w, tanh_ap(a + u.z), acc[2]);
        acc[3] = fmaf(w, tanh_ap(a + u.w), acc[3]);
        acc[4] = fmaf(w, tanh_ap(a + v.x), acc[4]);
        acc[5] = fmaf(w, tanh_ap(a + v.y), acc[5]);
        acc[6] = fmaf(w, tanh_ap(a + v.z), acc[6]);
        acc[7] = fmaf(w, tanh_ap(a + v.w), acc[7]);
    }

    float C = csh;
    int i  = i0 + ti;
    int jb = j0 + tg * 8;
#pragma unroll
    for (int c = 0; c < 8; c++) {
        int j = jb + c;
        if (j < NJ) outS[(size_t)i * OUT_LD + j] = acc[c] + C;
    }
}

// ---------------- k3: per-row softmax (in place) + per-row L1 loss partial ----------------
__global__ void __launch_bounds__(256) k3_softmax(float* __restrict__ outS,
                                                  const int* __restrict__ tgt) {
    __shared__ float red[256];
    __shared__ float red2[256];
    int i = blockIdx.x;
    int t = threadIdx.x;

    float s[5];
    float mx = -1e30f;
    int cnt = 0;
#pragma unroll
    for (int k = 0; k < 5; k++) {
        int j = t + 256 * k;
        if (j < NJ) {
            s[k] = outS[(size_t)i * OUT_LD + j];
            mx = fmaxf(mx, s[k]);
            cnt = k + 1;
        }
    }
    red[t] = mx;
    __syncthreads();
    for (int off = 128; off > 0; off >>= 1) {
        if (t < off) red[t] = fmaxf(red[t], red[t + off]);
        __syncthreads();
    }
    mx = red[0];
    __syncthreads();

    int tg = tgt[i];
    float e[5];
    float sum = 0.f, lo = 0.f;
    for (int k = 0; k < cnt; k++) {
        int j = t + 256 * k;
        e[k] = __expf(s[k] - mx);
        sum += e[k];
        float ind = (j == tg) ? 1.f : 0.f;
        lo += fabsf(s[k] - ind);
    }
    red[t] = sum;
    red2[t] = lo;
    __syncthreads();
    for (int off = 128; off > 0; off >>= 1) {
        if (t < off) {
            red[t]  += red[t + off];
            red2[t] += red2[t + off];
        }
        __syncthreads();
    }
    float inv = 1.0f / red[0];
    if (t == 0) g_rowloss[i] = red2[0];
    for (int k = 0; k < cnt; k++) {
        int j = t + 256 * k;
        outS[(size_t)i * OUT_LD + j] = e[k] * inv;
    }
}

// ---------------- k4: deterministic loss reduction ----------------
__global__ void __launch_bounds__(512) k4_loss(float* __restrict__ out) {
    __shared__ float red[512];
    int t = threadIdx.x;
    red[t] = g_rowloss[t] + g_rowloss[t + 512];
    __syncthreads();
    for (int off = 256; off > 0; off >>= 1) {
        if (t < off) red[t] += red[t + off];
        __syncthreads();
    }
    if (t == 0) out[0] = red[0] * (1.0f / (1024.0f * 1025.0f));
}

extern "C" void kernel_launch(void* const* d_in, const int* in_sizes, int n_in,
                              void* d_out, int out_size) {
    const float* sentence;
    const int*   tgt;
    const float* W1;
    const float* b1;
    const float* W2;
    const float* b2;

    // Resolve input ordering robustly via sizes:
    // dict order: [307200, 1024, 60000, 100, 100, 1]
    // arg  order: [307200, 60000, 100, 100, 1, 1024]
    if (n_in >= 6 && in_sizes[1] == 1024) {
        sentence = (const float*)d_in[0];
        tgt      = (const int*)d_in[1];
        W1       = (const float*)d_in[2];
        b1       = (const float*)d_in[3];
        W2       = (const float*)d_in[4];
        b2       = (const float*)d_in[5];
    } else {
        sentence = (const float*)d_in[0];
        W1       = (const float*)d_in[1];
        b1       = (const float*)d_in[2];
        W2       = (const float*)d_in[3];
        b2       = (const float*)d_in[4];
        tgt      = (const int*)d_in[5];
    }

    float* out    = (float*)d_out;
    float* scores = out + 1;   // output layout: [loss, score_matrix(1024x1025)]

    k0_prep<<<1, 128>>>(W2, b1, b2);
    k1_gemm<<<32, 256>>>(sentence, W1, b1);
    dim3 g2(17, 32);           // 17 j-tiles (64) x 32 i-tiles (32)
    k2_scores<<<g2, 256>>>(scores);
    k3_softmax<<<1024, 256>>>(scores, tgt);
    k4_loss<<<1, 512>>>(out);
}

// round 2
// speedup vs baseline: 1.8168x; 1.8168x over previous
#include <cuda_runtime.h>

#define NROW 1024
#define HDIM 300
#define MID  100
#define NJ   1025
#define OUT_LD 1025
#define MPAD 104          // MID padded to 8*13
#define S2P  1088         // s2T pitch (floats), covers j-tile reads to 1087
#define SCP  1088         // scores scratch pitch (floats)

// ---- device scratch (zero-initialized; pad regions stay 0) ----
__device__ __align__(16) float g_s1[NROW * MPAD];       // [i][m] = 0.5*s1, cols 100..103 = 0
__device__ __align__(16) float g_s2T[MID * S2P];        // [m][j] = 0.5*(s2+b1), j=0..1024
__device__ __align__(16) float2 g_w2d[MID];             // (0.5*w2, 0.5*w2)
__device__ __align__(16) float g_scores[NROW * SCP];    // raw scores scratch (aligned)
__device__ float g_C[1];
__device__ float g_rowloss[NROW];

// ================= k1: GEMM for s1 (64 blocks) + s2 (64 blocks) + prep (block 128) =================
// Block: 128 threads = 16 rows x 8 m-groups; thread owns 1 row x 13 contiguous m.
#define HC 60
__global__ void __launch_bounds__(128) k1_gemm(const float* __restrict__ sent,
                                               const float* __restrict__ W1,
                                               const float* __restrict__ b1,
                                               const float* __restrict__ W2,
                                               const float* __restrict__ b2) {
    int b = blockIdx.x;
    int tid = threadIdx.x;

    if (b == 128) {   // prep block
        __shared__ float red[128];
        float w = 0.f;
        if (tid < MID) {
            w = W2[tid];
            g_w2d[tid] = make_float2(0.5f * w, 0.5f * w);
            g_s2T[tid * S2P + 0] = 0.5f * b1[tid];   // j=0: pm row is zeros
        }
        red[tid] = w;
        __syncthreads();
        for (int s = 64; s > 0; s >>= 1) {
            if (tid < s) red[tid] += red[tid + s];
            __syncthreads();
        }
        if (tid == 0) g_C[0] = b2[0] + 0.5f * red[0];
        return;
    }

    __shared__ float4 rs4[16][16];      // rows x h4 (15 used)
    __shared__ float4 ws4[MPAD][16];    // m x h4 (transposed W1 chunk)

    bool isS1 = (b < 64);
    int r0 = (b & 63) * 16;
    int woff = isS1 ? 0 : HDIM;
    const float* src = sent + (size_t)r0 * HDIM;

    int r  = tid & 15;
    int mg = tid >> 4;
    int m0 = mg * 13;

    float acc[13];
#pragma unroll
    for (int c = 0; c < 13; c++) acc[c] = 0.f;

    for (int hc = 0; hc < HDIM; hc += HC) {
        // fill rs: 16 rows x 15 float4
        for (int q = tid; q < 16 * 15; q += 128) {
            int rr = q / 15, h4 = q % 15;
            rs4[rr][h4] = *(const float4*)(src + rr * HDIM + hc + h4 * 4);
        }
        // fill wsT: 104 m x 15 float4 (m>=100 zero)
        for (int q = tid; q < MPAD * 15; q += 128) {
            int m = q / 15, h4 = q % 15;
            float4 v = make_float4(0.f, 0.f, 0.f, 0.f);
            if (m < MID) v = *(const float4*)(W1 + m * (2 * HDIM) + woff + hc + h4 * 4);
            ws4[m][h4] = v;
        }
        __syncthreads();
#pragma unroll
        for (int h4 = 0; h4 < 15; h4++) {
            float4 rv = rs4[r][h4];
#pragma unroll
            for (int c = 0; c < 13; c++) {
                float4 wv = ws4[m0 + c][h4];
                acc[c] = fmaf(rv.x, wv.x, acc[c]);
                acc[c] = fmaf(rv.y, wv.y, acc[c]);
                acc[c] = fmaf(rv.z, wv.z, acc[c]);
                acc[c] = fmaf(rv.w, wv.w, acc[c]);
            }
        }
        __syncthreads();
    }

    if (isS1) {
        int i = r0 + r;
#pragma unroll
        for (int c = 0; c < 13; c++) {
            int m = m0 + c;
            if (m < MID) g_s1[i * MPAD + m] = 0.5f * acc[c];
        }
    } else {
        int j = r0 + r + 1;
#pragma unroll
        for (int c = 0; c < 13; c++) {
            int m = m0 + c;
            if (m < MID) g_s2T[m * S2P + j] = 0.5f * (acc[c] + b1[m]);
        }
    }
}

// ================= k2: pairwise scores — f16x2 tanh, fp32 accumulate =================
// One pair (2 elements): add.f32x2 -> cvt.f16x2 -> tanh.f16x2 (1 MUFU) -> 2x cvt.f32 -> fma.f32x2
__device__ __forceinline__ void pair_step(unsigned long long& acc, unsigned long long a2,
                                          unsigned long long p, unsigned long long w2) {
    asm volatile(
        "{\n\t"
        ".reg .b32 lo, hi, f0, f1, h2, t2;\n\t"
        ".reg .b16 q0, q1;\n\t"
        ".reg .b64 s, tf;\n\t"
        "add.rn.f32x2 s, %1, %2;\n\t"
        "mov.b64 {lo, hi}, s;\n\t"
        "cvt.rn.f16x2.f32 h2, hi, lo;\n\t"
        "tanh.approx.f16x2 t2, h2;\n\t"
        "mov.b32 {q0, q1}, t2;\n\t"
        "cvt.f32.f16 f0, q0;\n\t"
        "cvt.f32.f16 f1, q1;\n\t"
        "mov.b64 tf, {f0, f1};\n\t"
        "fma.rn.f32x2 %0, %3, tf, %0;\n\t"
        "}"
        : "+l"(acc)
        : "l"(a2), "l"(p), "l"(w2));
}

#define S2TP 36   // s2 tile pitch in float2 units (288B rows)
__global__ void __launch_bounds__(256) k2_scores() {
    __shared__ float s1t[32][MPAD];                       // 0.5*s1 tile
    __shared__ __align__(16) unsigned long long s2t[MID][S2TP]; // f32x2 pairs of 0.5*(s2+b1)
    __shared__ __align__(16) unsigned long long w2t[MID]; // duplicated 0.5*w2
    __shared__ float csh;

    int tid = threadIdx.x;
    int i0 = blockIdx.y * 32;
    int j0 = blockIdx.x * 64;

    for (int q = tid; q < 32 * MPAD; q += 256)
        s1t[q / MPAD][q % MPAD] = g_s1[(i0 + q / MPAD) * MPAD + (q % MPAD)];
    for (int q = tid; q < MID * 16; q += 256) {
        int m = q >> 4, f4 = q & 15;
        float4 v = *(const float4*)(g_s2T + m * S2P + j0 + f4 * 4);
        *((float4*)&s2t[m][0] + f4) = v;
    }
    if (tid < MID) {
        float2 w = g_w2d[tid];
        w2t[tid] = *(unsigned long long*)&w;
    }
    if (tid == 0) csh = g_C[0];
    __syncthreads();

    int ti = tid >> 3;      // i within tile
    int tg = tid & 7;       // 8 consecutive j
    unsigned long long acc0 = 0ull, acc1 = 0ull, acc2 = 0ull, acc3 = 0ull;

#pragma unroll 2
    for (int m = 0; m < MID; m++) {
        float a = s1t[ti][m];
        unsigned long long a2;
        asm("mov.b64 %0, {%1, %1};" : "=l"(a2) : "f"(a));
        unsigned long long w2 = w2t[m];
        ulonglong2 p01 = *((const ulonglong2*)&s2t[m][0] + 2 * tg);
        ulonglong2 p23 = *((const ulonglong2*)&s2t[m][0] + 2 * tg + 1);
        pair_step(acc0, a2, p01.x, w2);
        pair_step(acc1, a2, p01.y, w2);
        pair_step(acc2, a2, p23.x, w2);
        pair_step(acc3, a2, p23.y, w2);
    }

    float C = csh;
    float o[8];
    asm("mov.b64 {%0,%1}, %2;" : "=f"(o[0]), "=f"(o[1]) : "l"(acc0));
    asm("mov.b64 {%0,%1}, %2;" : "=f"(o[2]), "=f"(o[3]) : "l"(acc1));
    asm("mov.b64 {%0,%1}, %2;" : "=f"(o[4]), "=f"(o[5]) : "l"(acc2));
    asm("mov.b64 {%0,%1}, %2;" : "=f"(o[6]), "=f"(o[7]) : "l"(acc3));
    float* dst = g_scores + (size_t)(i0 + ti) * SCP + j0 + tg * 8;
    *(float4*)dst       = make_float4(o[0] + C, o[1] + C, o[2] + C, o[3] + C);
    *(float4*)(dst + 4) = make_float4(o[4] + C, o[5] + C, o[6] + C, o[7] + C);
}

// ================= k3: softmax + per-row L1 loss (shuffle reductions, float4 loads) =================
__global__ void __launch_bounds__(256) k3_softmax(float* __restrict__ out,
                                                  const int* __restrict__ tgt) {
    __shared__ float smax[8], ssum[8], sloss[8];
    int i = blockIdx.x, t = threadIdx.x;
    const float* row = g_scores + (size_t)i * SCP;
    float4 v = ((const float4*)row)[t];
    float ex = row[1024];

    float mx = fmaxf(fmaxf(v.x, v.y), fmaxf(v.z, v.w));
    mx = fmaxf(mx, ex);
#pragma unroll
    for (int off = 16; off > 0; off >>= 1)
        mx = fmaxf(mx, __shfl_xor_sync(0xffffffffu, mx, off));
    if ((t & 31) == 0) smax[t >> 5] = mx;
    __syncthreads();
    mx = smax[0];
#pragma unroll
    for (int w = 1; w < 8; w++) mx = fmaxf(mx, smax[w]);

    int tg = tgt[i];
    float4 e;
    e.x = __expf(v.x - mx);
    e.y = __expf(v.y - mx);
    e.z = __expf(v.z - mx);
    e.w = __expf(v.w - mx);
    float eex = __expf(ex - mx);
    float sum = e.x + e.y + e.z + e.w;
    int jb = 4 * t;
    float lo = fabsf(v.x - ((jb + 0 == tg) ? 1.f : 0.f))
             + fabsf(v.y - ((jb + 1 == tg) ? 1.f : 0.f))
             + fabsf(v.z - ((jb + 2 == tg) ? 1.f : 0.f))
             + fabsf(v.w - ((jb + 3 == tg) ? 1.f : 0.f));
    if (t == 0) {
        sum += eex;
        lo  += fabsf(ex - ((1024 == tg) ? 1.f : 0.f));
    }
#pragma unroll
    for (int off = 16; off > 0; off >>= 1) {
        sum += __shfl_xor_sync(0xffffffffu, sum, off);
        lo  += __shfl_xor_sync(0xffffffffu, lo, off);
    }
    if ((t & 31) == 0) { ssum[t >> 5] = sum; sloss[t >> 5] = lo; }
    __syncthreads();
    float st = 0.f, lt = 0.f;
#pragma unroll
    for (int w = 0; w < 8; w++) { st += ssum[w]; lt += sloss[w]; }

    float inv = 1.0f / st;
    float* o = out + 1 + (size_t)i * OUT_LD + jb;
    o[0] = e.x * inv;
    o[1] = e.y * inv;
    o[2] = e.z * inv;
    o[3] = e.w * inv;
    if (t == 0) {
        out[1 + (size_t)i * OUT_LD + 1024] = eex * inv;
        g_rowloss[i] = lt;
    }
}

// ================= k4: deterministic loss reduction =================
__global__ void __launch_bounds__(512) k4_loss(float* __restrict__ out) {
    __shared__ float red[512];
    int t = threadIdx.x;
    red[t] = g_rowloss[t] + g_rowloss[t + 512];
    __syncthreads();
    for (int off = 256; off > 0; off >>= 1) {
        if (t < off) red[t] += red[t + off];
        __syncthreads();
    }
    if (t == 0) out[0] = red[0] * (1.0f / (1024.0f * 1025.0f));
}

extern "C" void kernel_launch(void* const* d_in, const int* in_sizes, int n_in,
                              void* d_out, int out_size) {
    const float* sentence;
    const int*   tgt;
    const float* W1;
    const float* b1;
    const float* W2;
    const float* b2;

    if (n_in >= 6 && in_sizes[1] == 1024) {
        sentence = (const float*)d_in[0];
        tgt      = (const int*)d_in[1];
        W1       = (const float*)d_in[2];
        b1       = (const float*)d_in[3];
        W2       = (const float*)d_in[4];
        b2       = (const float*)d_in[5];
    } else {
        sentence = (const float*)d_in[0];
        W1       = (const float*)d_in[1];
        b1       = (const float*)d_in[2];
        W2       = (const float*)d_in[3];
        b2       = (const float*)d_in[4];
        tgt      = (const int*)d_in[5];
    }

    float* out = (float*)d_out;

    k1_gemm<<<129, 128>>>(sentence, W1, b1, W2, b2);
    dim3 g2(17, 32);
    k2_scores<<<g2, 256>>>();
    k3_softmax<<<1024, 256>>>(out, tgt);
    k4_loss<<<1, 512>>>(out);
}